// round 6
// baseline (speedup 1.0000x reference)
#include <cuda_runtime.h>
#include <cstdint>
#include <math.h>

#define NF 64
#define Bn 5000
#define Ln 10
#define Tn 25
#define Kn 8

typedef unsigned long long ull;

// Scratch: u-table [t][b][l][k] (40 MB) so gather rows are contiguous 32B.
__device__ float g_u[(size_t)Tn * Bn * Ln * Kn];

// ---------------------------------------------------------------------------
// Kernel 1: fused cholesky-diag + AR(1) scan, float4-vectorized.
// ---------------------------------------------------------------------------
__global__ void __launch_bounds__(256)
scan_kernel(const float* __restrict__ eps,
            const float* __restrict__ raw_rho,
            const float* __restrict__ Sigma) {
    __shared__ float sA[Kn][Ln * Ln];
    __shared__ float sd[Ln][Kn];

    int tid = threadIdx.x;
    for (int i = tid; i < Kn * Ln * Ln; i += 256)
        ((float*)sA)[i] = Sigma[i];
    __syncthreads();

    if (tid < Kn) {
        float* A = sA[tid];
        for (int i = 0; i < Ln; i++) {
            for (int j = 0; j < i; j++) {
                float s = A[i * Ln + j];
                for (int p = 0; p < j; p++) s -= A[i * Ln + p] * A[j * Ln + p];
                A[i * Ln + j] = __fdividef(s, A[j * Ln + j]);
            }
            float s = A[i * Ln + i];
            for (int p = 0; p < i; p++) s -= A[i * Ln + p] * A[i * Ln + p];
            float dii = sqrtf(s);
            A[i * Ln + i] = dii;
            sd[i][tid] = dii;
        }
    }
    __syncthreads();

    int idx = blockIdx.x * blockDim.x + tid;        // (b, l, kq)
    if (idx >= Bn * Ln * 2) return;
    int kq = idx & 1;
    int l  = (idx >> 1) % Ln;
    int b  = idx / (2 * Ln);

    float4 rr = *(const float4*)(raw_rho + l * Kn + kq * 4);
    float4 rho = make_float4(tanhf(rr.x), tanhf(rr.y), tanhf(rr.z), tanhf(rr.w));
    float4 d = *(float4*)&sd[l][kq * 4];

    const float4* e = (const float4*)(eps + ((size_t)(b * Ln + l) * Tn) * Kn + kq * 4);
    float4* up = (float4*)(g_u + (size_t)(b * Ln + l) * Kn + kq * 4);
    const size_t ustep = (size_t)Bn * Ln * Kn / 4;

    float4 u = __ldcs(&e[0]);
    up[0] = u;
#pragma unroll
    for (int t = 1; t < Tn; t++) {
        float4 ev = __ldcs(&e[t * 2]);
        u.x = fmaf(rho.x, u.x, d.x * ev.x);
        u.y = fmaf(rho.y, u.y, d.y * ev.y);
        u.z = fmaf(rho.z, u.z, d.z * ev.z);
        u.w = fmaf(rho.w, u.w, d.w * ev.w);
        up[(size_t)t * ustep] = u;
    }
}

// ---------------------------------------------------------------------------
// Kernel 2: out[n,:] = X[n,:] @ beta + u[s,b,l,:]
// One block = 256 rows. X tile (64 KB) staged through smem with XOR swizzle
// (slot = chunk ^ (row&7)): coalesced GMEM loads AND conflict-free per-row
// LDS.128 reads. beta (2 KB) in smem, read as free LDS.128 broadcasts.
// Each thread computes its whole row: no shuffles, no reductions.
// ---------------------------------------------------------------------------
#define FMA2(d_, a_, b_, c_) \
    asm("fma.rn.f32x2 %0, %1, %2, %3;" : "=l"(d_) : "l"(a_), "l"(b_), "l"(c_))

__device__ __forceinline__ ull dupf(float x) {
    unsigned int w = __float_as_uint(x);
    ull q;
    asm("mov.b64 %0, {%1,%2};" : "=l"(q) : "r"(w), "r"(w));
    return q;
}

#define TILE_BYTES 65536            // 256 rows * 64 floats * 4B
#define SMEM_TOTAL (TILE_BYTES + 2048)

__global__ void __launch_bounds__(256, 3)
main_kernel(const float* __restrict__ X,
            const int* __restrict__ batter_ids,
            const int* __restrict__ league_ids,
            const int* __restrict__ season_ids,
            const float* __restrict__ beta,
            float* __restrict__ out, int N) {
    extern __shared__ char smem_raw[];
    float4* sx = (float4*)smem_raw;                       // 4096 float4
    ull*    sb = (ull*)(smem_raw + TILE_BYTES);           // 256 ull
    const ulonglong2* sb2 = (const ulonglong2*)sb;

    int tid = threadIdx.x;

    // beta -> smem (coalesced, 2 KB)
    sb[tid] = ((const ull*)beta)[tid];

    // stage X tile: thread i loads float4 linear indices i, i+256, ...
    // store at slot = chunk ^ (row & 7)  (XOR swizzle, conflict-free)
    size_t base = (size_t)blockIdx.x * 256;               // first row of tile
    const float4* xg = (const float4*)X;
#pragma unroll
    for (int k = 0; k < 16; k++) {
        int f = tid + k * 256;
        int row = f >> 4;
        int c   = f & 15;
        size_t gr = base + row;
        if (gr >= (size_t)N) gr = (size_t)N - 1;          // clamp (dup rows unused)
        float4 v = __ldcs(&xg[gr * 16 + c]);
        sx[row * 16 + (c ^ (row & 7))] = v;
    }
    __syncthreads();

    int n  = (int)base + tid;                             // this thread's row
    int cn = min(n, N - 1);

    // gather ids + u early (independent of the FMA loop)
    int s = season_ids[cn], b = batter_ids[cn], l = league_ids[cn];
    const float4* up = (const float4*)(
        g_u + ((size_t)(s * Bn + b) * Ln + l) * Kn);
    float4 u0 = up[0];
    float4 u1 = up[1];

    ull acc0 = 0, acc1 = 0, acc2 = 0, acc3 = 0;
    int rsw = tid & 7;
    const float4* myrow = sx + tid * 16;

#pragma unroll
    for (int cc = 0; cc < 16; cc++) {
        float4 xv = myrow[cc ^ rsw];                      // chunk cc (deswizzle)
        float xs[4] = {xv.x, xv.y, xv.z, xv.w};
#pragma unroll
        for (int r = 0; r < 4; r++) {
            int j = cc * 4 + r;                           // feature index
            ull q = dupf(xs[r]);
            ulonglong2 b01 = sb2[j * 2];                  // beta[j][0..3] (bcast)
            ulonglong2 b23 = sb2[j * 2 + 1];              // beta[j][4..7]
            FMA2(acc0, q, b01.x, acc0);
            FMA2(acc1, q, b01.y, acc1);
            FMA2(acc2, q, b23.x, acc2);
            FMA2(acc3, q, b23.y, acc3);
        }
    }

    if (n < N) {
        float f0, f1, f2, f3, f4, f5, f6, f7;
        asm("mov.b64 {%0,%1}, %2;" : "=f"(f0), "=f"(f1) : "l"(acc0));
        asm("mov.b64 {%0,%1}, %2;" : "=f"(f2), "=f"(f3) : "l"(acc1));
        asm("mov.b64 {%0,%1}, %2;" : "=f"(f4), "=f"(f5) : "l"(acc2));
        asm("mov.b64 {%0,%1}, %2;" : "=f"(f6), "=f"(f7) : "l"(acc3));
        float4 o0 = make_float4(f0 + u0.x, f1 + u0.y, f2 + u0.z, f3 + u0.w);
        float4 o1 = make_float4(f4 + u1.x, f5 + u1.y, f6 + u1.z, f7 + u1.w);
        float4* op = (float4*)(out + (size_t)n * Kn);
        op[0] = o0;
        op[1] = o1;
    }
}

// ---------------------------------------------------------------------------
extern "C" void kernel_launch(void* const* d_in, const int* in_sizes, int n_in,
                              void* d_out, int out_size) {
    const float* X       = (const float*)d_in[0];
    const int*   bid     = (const int*)d_in[1];
    const int*   lid     = (const int*)d_in[2];
    const int*   sid     = (const int*)d_in[3];
    const float* beta    = (const float*)d_in[4];
    const float* raw_rho = (const float*)d_in[5];
    const float* Sigma   = (const float*)d_in[6];
    const float* eps     = (const float*)d_in[7];
    float*       out     = (float*)d_out;

    const int N = in_sizes[1];

    static int smem_set = 0;
    if (!smem_set) {
        cudaFuncSetAttribute(main_kernel,
                             cudaFuncAttributeMaxDynamicSharedMemorySize,
                             SMEM_TOTAL);
        smem_set = 1;
    }

    int chains4 = Bn * Ln * 2;
    scan_kernel<<<(chains4 + 255) / 256, 256>>>(eps, raw_rho, Sigma);

    int blocks = (N + 255) / 256;
    main_kernel<<<blocks, 256, SMEM_TOTAL>>>(X, bid, lid, sid, beta, out, N);
}